// round 4
// baseline (speedup 1.0000x reference)
#include <cuda_runtime.h>
#include <math.h>

#define T_MAX 1000
#define B_ 64
#define D_ 128
#define N_ 512
#define O_ 10

__device__ float g_Iext[(size_t)T_MAX * B_ * N_];  // 131 MB scratch
__device__ float g_WT[N_ * N_];                    // W_rec transposed

// ---------------- bulk zero fill (two regions) ----------------
__global__ void zfill(float4* __restrict__ a, size_t na, float4* __restrict__ b, size_t nb) {
    size_t i = (size_t)blockIdx.x * blockDim.x + threadIdx.x;
    size_t stride = (size_t)gridDim.x * blockDim.x;
    float4 z = make_float4(0.f, 0.f, 0.f, 0.f);
    for (; i < na + nb; i += stride) {
        if (i < na) a[i] = z;
        else        b[i - na] = z;
    }
}

// ---------------- transpose W_rec -> g_WT ----------------
__global__ void wt_transpose(const float* __restrict__ W) {
    __shared__ float tile[32][33];
    int bx = blockIdx.x * 32, by = blockIdx.y * 32;
    int tx = threadIdx.x, ty = threadIdx.y;
#pragma unroll
    for (int i = 0; i < 32; i += 8)
        tile[ty + i][tx] = W[(size_t)(by + ty + i) * N_ + (bx + tx)];
    __syncthreads();
#pragma unroll
    for (int i = 0; i < 32; i += 8)
        g_WT[(size_t)(bx + ty + i) * N_ + (by + tx)] = tile[tx][ty + i];
}

// ---------------- I_ext GEMM: split-K, 2 CTAs/SM, packed f32x2 FMA ----------------
#define GBM 128
#define GBN 128
#define GKH 64
#define A_LD 68
#define B_LD 130
#define GEMM_SMEM ((GBM * A_LD + GKH * B_LD) * 4)

__global__ __launch_bounds__(256, 2) void iext_gemm(const float* __restrict__ X,
                                                    const float* __restrict__ Win,
                                                    const float* __restrict__ sc_p) {
    extern __shared__ float sm[];
    float* As = sm;                  // [GBM][A_LD]  m-major, 64 k-cols per phase
    float* Bs = sm + GBM * A_LD;     // [GKH][B_LD]  k-major
    const float sc = __ldg(sc_p);
    const int m0 = blockIdx.x * GBM;
    const int n0 = blockIdx.y * GBN;
    const int tid = threadIdx.x;

    const int tm  = (tid >> 4) * 8;
    const int tn2 = (tid & 15) * 2;
    unsigned long long acc[8][4];
#pragma unroll
    for (int i = 0; i < 8; ++i)
#pragma unroll
        for (int j = 0; j < 4; ++j) acc[i][j] = 0ull;

    const int c4 = (tid & 15) * 4;
    const int rbase = tid >> 4;

#pragma unroll 1
    for (int kb = 0; kb < 2; ++kb) {
        if (kb) __syncthreads();
        // A tile: 128 rows x 64 cols
#pragma unroll
        for (int p = 0; p < 8; ++p) {
            int m = rbase + p * 16;
            float4 xv = *(const float4*)(X + (size_t)(m0 + m) * D_ + kb * GKH + c4);
            xv.x *= sc; xv.y *= sc; xv.z *= sc; xv.w *= sc;
            *(float4*)(As + m * A_LD + c4) = xv;
        }
        // B tile: 128 n-rows x 64 k-cols, transposed to k-major
#pragma unroll
        for (int p = 0; p < 8; ++p) {
            int id = tid + p * 256;
            int nn = id >> 4;
            int cc = (id & 15) * 4;
            float4 wv = *(const float4*)(Win + (size_t)(n0 + nn) * D_ + kb * GKH + cc);
            Bs[(cc + 0) * B_LD + nn] = wv.x;
            Bs[(cc + 1) * B_LD + nn] = wv.y;
            Bs[(cc + 2) * B_LD + nn] = wv.z;
            Bs[(cc + 3) * B_LD + nn] = wv.w;
        }
        __syncthreads();

#pragma unroll 2
        for (int k = 0; k < GKH; ++k) {
            unsigned long long b2[4];
#pragma unroll
            for (int j = 0; j < 4; ++j) {
                float2 bb = *(const float2*)(Bs + k * B_LD + tn2 + 32 * j);
                asm("mov.b64 %0, {%1,%2};" : "=l"(b2[j]) : "f"(bb.x), "f"(bb.y));
            }
#pragma unroll
            for (int i = 0; i < 8; ++i) {
                float a = As[(tm + i) * A_LD + k];
                unsigned long long a2;
                asm("mov.b64 %0, {%1,%1};" : "=l"(a2) : "f"(a));
#pragma unroll
                for (int j = 0; j < 4; ++j)
                    asm("fma.rn.f32x2 %0, %1, %2, %0;" : "+l"(acc[i][j]) : "l"(a2), "l"(b2[j]));
            }
        }
    }
#pragma unroll
    for (int i = 0; i < 8; ++i) {
        float* orow = g_Iext + (size_t)(m0 + tm + i) * N_ + n0 + tn2;
#pragma unroll
        for (int j = 0; j < 4; ++j) {
            float2 o;
            asm("mov.b64 {%0,%1}, %2;" : "=f"(o.x), "=f"(o.y) : "l"(acc[i][j]));
            *(float2*)(orow + 32 * j) = o;
        }
    }
}

// ---------------- sim: 1 CTA/batch, 128 threads, 4 neurons/thread ----------------
__global__ __launch_bounds__(128, 1) void sim_kernel(
    const float* __restrict__ Wout, const float* __restrict__ bout,
    const float* __restrict__ osc_p,
    float* __restrict__ out, float* __restrict__ spk, float* __restrict__ vlt,
    float* __restrict__ pscO, float* __restrict__ filt,
    int T, int startT, int writeHist,
    float e_syn, float e_asc, float alpha)
{
    const int b = blockIdx.x;
    const int tid = threadIdx.x;
    const int lane = tid & 31, wid = tid >> 5;
    const int n0 = tid * 4;
    const int mword = tid >> 3;            // smask word owned by this thread's neurons
    const int mbit0 = (tid & 7) * 4;

    __shared__ unsigned smask[2][16];
    __shared__ float sred[4];
    if (tid < 16) { smask[0][tid] = 0u; smask[1][tid] = 0u; }
    __syncthreads();

    const float a_mem = 0.05f, VR = -60.0f, VTH = -45.0f, KP = 0.2f, AA = -0.2f;
    const float oma = 1.0f - alpha;
    float v[4], asc[4], rr[4], psc[4], f[4], fsum[4];
    int rcnt[4];
#pragma unroll
    for (int k = 0; k < 4; ++k) {
        v[k] = VR; asc[k] = 0.f; rr[k] = 0.f; psc[k] = 0.f;
        f[k] = 0.f; fsum[k] = 0.f; rcnt[k] = 0;
    }
    const int BN = B_ * N_;
    const float* Ibase = g_Iext + (size_t)b * N_ + n0;

    // 8-deep prefetch ring of float4 I_ext loads
    float4 pre[8];
#pragma unroll
    for (int j = 0; j < 8; ++j)
        pre[j] = (j < T) ? __ldg((const float4*)(Ibase + (size_t)j * BN))
                         : make_float4(0.f, 0.f, 0.f, 0.f);

    int rb = 0, prev_any = 0;
    const int Tm = T & ~7;
    for (int t0 = 0; t0 < Tm; t0 += 8) {
#pragma unroll
        for (int j = 0; j < 8; ++j) {
            const int tt = t0 + j;
            const float4 It4 = pre[j];
            if (tt + 8 < T) pre[j] = __ldg((const float4*)(Ibase + (size_t)(tt + 8) * BN));

            float rec[4] = {0.f, 0.f, 0.f, 0.f};
            if (prev_any) {
#pragma unroll 1
                for (int w = 0; w < 16; ++w) {
                    unsigned m = smask[rb][w];
                    while (m) {
                        int bit = __ffs((int)m) - 1;
                        m &= (m - 1);
                        float4 wv = *(const float4*)(g_WT + ((size_t)(w * 32 + bit) << 9) + n0);
                        rec[0] += wv.x; rec[1] += wv.y; rec[2] += wv.z; rec[3] += wv.w;
                    }
                }
            }

            const float Iin[4] = {It4.x, It4.y, It4.z, It4.w};
            float s[4];
            int spiked = 0;
#pragma unroll
            for (int k = 0; k < 4; ++k) {
                rr[k] = rr[k] * e_syn + rec[k];
                psc[k] = psc[k] * e_syn + KP * rr[k];
                v[k] = v[k] + a_mem * (VR - v[k]) + a_mem * (Iin[k] + psc[k] + asc[k]);
                bool inref = rcnt[k] > 0;
                if (inref) v[k] = VR;
                s[k] = (v[k] - VTH >= 0.0f) ? 1.0f : 0.0f;
                if (s[k] > 0.0f) { v[k] = VR; rcnt[k] = 5; spiked = 1; }
                else             { rcnt[k] = inref ? rcnt[k] - 1 : 0; }
                asc[k] = asc[k] * e_asc + AA * s[k];
                f[k] = (tt == 0) ? s[k] : (alpha * f[k] + oma * s[k]);
                if (tt >= startT) fsum[k] += f[k];
            }

            if (writeHist) {
                size_t idx = (size_t)tt * BN + (size_t)b * N_ + n0;
                *(float4*)(vlt + idx) = make_float4(v[0], v[1], v[2], v[3]);
#pragma unroll
                for (int k = 0; k < 4; ++k) {
                    if (s[k] != 0.0f)   spk[idx + k] = s[k];
                    if (psc[k] != 0.0f) pscO[idx + k] = psc[k];
                    if (f[k] != 0.0f)   filt[idx + k] = f[k];
                }
            }

            int any = __syncthreads_or(spiked);
            if (any | prev_any) {
                const int wb = rb ^ 1;
                if (prev_any && tid < 16) smask[rb][tid] = 0u;  // consumed -> re-zero
                if (spiked) {
                    unsigned bits = 0u;
#pragma unroll
                    for (int k = 0; k < 4; ++k)
                        if (s[k] != 0.0f) bits |= 1u << (mbit0 + k);
                    atomicOr(&smask[wb][mword], bits);
                }
                __syncthreads();
                if (any) rb = wb;
            }
            prev_any = any;
        }
    }
    // remainder (T not multiple of 8): latency-exposed, <=7 steps
    for (int tt = Tm; tt < T; ++tt) {
        const float4 It4 = __ldg((const float4*)(Ibase + (size_t)tt * BN));
        float rec[4] = {0.f, 0.f, 0.f, 0.f};
        if (prev_any) {
#pragma unroll 1
            for (int w = 0; w < 16; ++w) {
                unsigned m = smask[rb][w];
                while (m) {
                    int bit = __ffs((int)m) - 1;
                    m &= (m - 1);
                    float4 wv = *(const float4*)(g_WT + ((size_t)(w * 32 + bit) << 9) + n0);
                    rec[0] += wv.x; rec[1] += wv.y; rec[2] += wv.z; rec[3] += wv.w;
                }
            }
        }
        const float Iin[4] = {It4.x, It4.y, It4.z, It4.w};
        float s[4];
        int spiked = 0;
#pragma unroll
        for (int k = 0; k < 4; ++k) {
            rr[k] = rr[k] * e_syn + rec[k];
            psc[k] = psc[k] * e_syn + KP * rr[k];
            v[k] = v[k] + a_mem * (VR - v[k]) + a_mem * (Iin[k] + psc[k] + asc[k]);
            bool inref = rcnt[k] > 0;
            if (inref) v[k] = VR;
            s[k] = (v[k] - VTH >= 0.0f) ? 1.0f : 0.0f;
            if (s[k] > 0.0f) { v[k] = VR; rcnt[k] = 5; spiked = 1; }
            else             { rcnt[k] = inref ? rcnt[k] - 1 : 0; }
            asc[k] = asc[k] * e_asc + AA * s[k];
            f[k] = (tt == 0) ? s[k] : (alpha * f[k] + oma * s[k]);
            if (tt >= startT) fsum[k] += f[k];
        }
        if (writeHist) {
            size_t idx = (size_t)tt * BN + (size_t)b * N_ + n0;
            *(float4*)(vlt + idx) = make_float4(v[0], v[1], v[2], v[3]);
#pragma unroll
            for (int k = 0; k < 4; ++k) {
                if (s[k] != 0.0f)   spk[idx + k] = s[k];
                if (psc[k] != 0.0f) pscO[idx + k] = psc[k];
                if (f[k] != 0.0f)   filt[idx + k] = f[k];
            }
        }
        int any = __syncthreads_or(spiked);
        if (any | prev_any) {
            const int wb = rb ^ 1;
            if (prev_any && tid < 16) smask[rb][tid] = 0u;
            if (spiked) {
                unsigned bits = 0u;
#pragma unroll
                for (int k = 0; k < 4; ++k)
                    if (s[k] != 0.0f) bits |= 1u << (mbit0 + k);
                atomicOr(&smask[wb][mword], bits);
            }
            __syncthreads();
            if (any) rb = wb;
        }
        prev_any = any;
    }

    // readout
    const float cnt = (float)(T - startT);
    const float osc = __ldg(osc_p);
    float a[4];
#pragma unroll
    for (int k = 0; k < 4; ++k) a[k] = (fsum[k] / cnt) * osc;
#pragma unroll 1
    for (int o = 0; o < O_; ++o) {
        float4 w4 = *(const float4*)(Wout + (size_t)o * N_ + n0);
        float val = a[0] * w4.x + a[1] * w4.y + a[2] * w4.z + a[3] * w4.w;
#pragma unroll
        for (int off = 16; off > 0; off >>= 1)
            val += __shfl_down_sync(0xffffffffu, val, off);
        if (lane == 0) sred[wid] = val;
        __syncthreads();
        if (tid == 0)
            out[b * O_ + o] = sred[0] + sred[1] + sred[2] + sred[3] + __ldg(bout + o);
        __syncthreads();
    }
}

extern "C" void kernel_launch(void* const* d_in, const int* in_sizes, int n_in,
                              void* d_out, int out_size) {
    const float* x    = (const float*)d_in[0];
    const float* Win  = (const float*)d_in[1];
    const float* isc  = (const float*)d_in[2];
    const float* Wrec = (const float*)d_in[3];
    const float* Wout = (const float*)d_in[4];
    const float* bout = (const float*)d_in[5];
    const float* osc  = (const float*)d_in[6];

    const int T = in_sizes[0] / (B_ * D_);
    float* out = (float*)d_out;
    const size_t TBN = (size_t)T * B_ * N_;
    const long long fullsz = (long long)B_ * O_ + 4LL * (long long)TBN;
    const int writeHist = ((long long)out_size >= fullsz) ? 1 : 0;
    float* spk = out + B_ * O_;
    float* vlt = spk + TBN;
    float* psc = vlt + TBN;
    float* flt = psc + TBN;

    const float e_syn = (float)exp((double)(-1.0f / 5.0f));
    const float e_asc = (float)exp((double)(-1.0f / 700.0f));
    const float alpha = (float)exp((double)(-1.0f / 20.0f));
    // int(T * (1.0 - 0.8)) truncates (float artifact): 199 for T=1000
    const int startT = (int)((double)T * (1.0 - 0.8));

    cudaFuncSetAttribute(iext_gemm, cudaFuncAttributeMaxDynamicSharedMemorySize, GEMM_SMEM);
    iext_gemm<<<dim3((T * B_) / GBM, N_ / GBN), 256, GEMM_SMEM>>>(x, Win, isc);

    // zero-fill spk (TBN) and psc+filt (2*TBN contiguous) — sim writes them sparsely
    if (writeHist)
        zfill<<<2048, 256>>>((float4*)spk, TBN / 4, (float4*)psc, (2 * TBN) / 4);

    wt_transpose<<<dim3(16, 16), dim3(32, 8)>>>(Wrec);

    sim_kernel<<<B_, 128>>>(Wout, bout, osc, out, spk, vlt, psc, flt,
                            T, startT, writeHist, e_syn, e_asc, alpha);
}

// round 5
// speedup vs baseline: 1.0064x; 1.0064x over previous
#include <cuda_runtime.h>
#include <math.h>

#define T_MAX 1000
#define B_ 64
#define D_ 128
#define N_ 512
#define O_ 10

__device__ float g_Iext[(size_t)T_MAX * B_ * N_];  // 131 MB scratch
__device__ float g_WT[N_ * N_];                    // W_rec transposed

// ---------------- bulk zero fill (two regions) ----------------
__global__ void zfill(float4* __restrict__ a, size_t na, float4* __restrict__ b, size_t nb) {
    size_t i = (size_t)blockIdx.x * blockDim.x + threadIdx.x;
    size_t stride = (size_t)gridDim.x * blockDim.x;
    float4 z = make_float4(0.f, 0.f, 0.f, 0.f);
    for (; i < na + nb; i += stride) {
        if (i < na) a[i] = z;
        else        b[i - na] = z;
    }
}

// ---------------- transpose W_rec -> g_WT ----------------
__global__ void wt_transpose(const float* __restrict__ W) {
    __shared__ float tile[32][33];
    int bx = blockIdx.x * 32, by = blockIdx.y * 32;
    int tx = threadIdx.x, ty = threadIdx.y;
#pragma unroll
    for (int i = 0; i < 32; i += 8)
        tile[ty + i][tx] = W[(size_t)(by + ty + i) * N_ + (bx + tx)];
    __syncthreads();
#pragma unroll
    for (int i = 0; i < 32; i += 8)
        g_WT[(size_t)(bx + ty + i) * N_ + (by + tx)] = tile[tx][ty + i];
}

// ---------------- I_ext GEMM: split-K, 2 CTAs/SM, packed f32x2 FMA ----------------
#define GBM 128
#define GBN 128
#define GKH 64
#define A_LD 68
#define B_LD 130
#define GEMM_SMEM ((GBM * A_LD + GKH * B_LD) * 4)

__global__ __launch_bounds__(256, 2) void iext_gemm(const float* __restrict__ X,
                                                    const float* __restrict__ Win,
                                                    const float* __restrict__ sc_p) {
    extern __shared__ float sm[];
    float* As = sm;                  // [GBM][A_LD]  m-major, 64 k-cols per phase
    float* Bs = sm + GBM * A_LD;     // [GKH][B_LD]  k-major
    const float sc = __ldg(sc_p);
    const int m0 = blockIdx.x * GBM;
    const int n0 = blockIdx.y * GBN;
    const int tid = threadIdx.x;

    const int tm  = (tid >> 4) * 8;
    const int tn2 = (tid & 15) * 2;
    unsigned long long acc[8][4];
#pragma unroll
    for (int i = 0; i < 8; ++i)
#pragma unroll
        for (int j = 0; j < 4; ++j) acc[i][j] = 0ull;

    const int c4 = (tid & 15) * 4;
    const int rbase = tid >> 4;

#pragma unroll 1
    for (int kb = 0; kb < 2; ++kb) {
        if (kb) __syncthreads();
        // A tile: 128 rows x 64 cols
#pragma unroll
        for (int p = 0; p < 8; ++p) {
            int m = rbase + p * 16;
            float4 xv = *(const float4*)(X + (size_t)(m0 + m) * D_ + kb * GKH + c4);
            xv.x *= sc; xv.y *= sc; xv.z *= sc; xv.w *= sc;
            *(float4*)(As + m * A_LD + c4) = xv;
        }
        // B tile: 128 n-rows x 64 k-cols, transposed to k-major
#pragma unroll
        for (int p = 0; p < 8; ++p) {
            int id = tid + p * 256;
            int nn = id >> 4;
            int cc = (id & 15) * 4;
            float4 wv = *(const float4*)(Win + (size_t)(n0 + nn) * D_ + kb * GKH + cc);
            Bs[(cc + 0) * B_LD + nn] = wv.x;
            Bs[(cc + 1) * B_LD + nn] = wv.y;
            Bs[(cc + 2) * B_LD + nn] = wv.z;
            Bs[(cc + 3) * B_LD + nn] = wv.w;
        }
        __syncthreads();

#pragma unroll 2
        for (int k = 0; k < GKH; ++k) {
            unsigned long long b2[4];
#pragma unroll
            for (int j = 0; j < 4; ++j) {
                float2 bb = *(const float2*)(Bs + k * B_LD + tn2 + 32 * j);
                asm("mov.b64 %0, {%1,%2};" : "=l"(b2[j]) : "f"(bb.x), "f"(bb.y));
            }
#pragma unroll
            for (int i = 0; i < 8; ++i) {
                float a = As[(tm + i) * A_LD + k];
                unsigned long long a2;
                asm("mov.b64 %0, {%1,%1};" : "=l"(a2) : "f"(a));
#pragma unroll
                for (int j = 0; j < 4; ++j)
                    asm("fma.rn.f32x2 %0, %1, %2, %0;" : "+l"(acc[i][j]) : "l"(a2), "l"(b2[j]));
            }
        }
    }
#pragma unroll
    for (int i = 0; i < 8; ++i) {
        float* orow = g_Iext + (size_t)(m0 + tm + i) * N_ + n0 + tn2;
#pragma unroll
        for (int j = 0; j < 4; ++j) {
            float2 o;
            asm("mov.b64 {%0,%1}, %2;" : "=f"(o.x), "=f"(o.y) : "l"(acc[i][j]));
            *(float2*)(orow + 32 * j) = o;
        }
    }
}

// ---------------- sim: 1 CTA/batch, 128 threads, 4 neurons/thread ----------------
__global__ __launch_bounds__(128, 1) void sim_kernel(
    const float* __restrict__ Wout, const float* __restrict__ bout,
    const float* __restrict__ osc_p,
    float* __restrict__ out, float* __restrict__ spk, float* __restrict__ vlt,
    float* __restrict__ pscO, float* __restrict__ filt,
    int T, int startT, int writeHist,
    float e_syn, float e_asc, float alpha)
{
    const int b = blockIdx.x;
    const int tid = threadIdx.x;
    const int lane = tid & 31, wid = tid >> 5;
    const int n0 = tid * 4;
    const int mword = tid >> 3;            // smask word owned by this thread's neurons
    const int mbit0 = (tid & 7) * 4;

    __shared__ unsigned smask[2][16];
    __shared__ float sred[4];
    if (tid < 16) { smask[0][tid] = 0u; smask[1][tid] = 0u; }
    __syncthreads();

    const float a_mem = 0.05f, VR = -60.0f, VTH = -45.0f, KP = 0.2f, AA = -0.2f;
    const float oma = 1.0f - alpha;
    float v[4], asc[4], rr[4], psc[4], f[4], fsum[4];
    int rcnt[4];
#pragma unroll
    for (int k = 0; k < 4; ++k) {
        v[k] = VR; asc[k] = 0.f; rr[k] = 0.f; psc[k] = 0.f;
        f[k] = 0.f; fsum[k] = 0.f; rcnt[k] = 0;
    }
    const int BN = B_ * N_;
    const float* Ibase = g_Iext + (size_t)b * N_ + n0;

    // 8-deep prefetch ring of float4 I_ext loads
    float4 pre[8];
#pragma unroll
    for (int j = 0; j < 8; ++j)
        pre[j] = (j < T) ? __ldg((const float4*)(Ibase + (size_t)j * BN))
                         : make_float4(0.f, 0.f, 0.f, 0.f);

    int rb = 0, prev_any = 0;
    const int Tm = T & ~7;
    for (int t0 = 0; t0 < Tm; t0 += 8) {
#pragma unroll
        for (int j = 0; j < 8; ++j) {
            const int tt = t0 + j;
            const float4 It4 = pre[j];
            if (tt + 8 < T) pre[j] = __ldg((const float4*)(Ibase + (size_t)(tt + 8) * BN));

            float rec[4] = {0.f, 0.f, 0.f, 0.f};
            if (prev_any) {
#pragma unroll 1
                for (int w = 0; w < 16; ++w) {
                    unsigned m = smask[rb][w];
                    while (m) {
                        int bit = __ffs((int)m) - 1;
                        m &= (m - 1);
                        float4 wv = *(const float4*)(g_WT + ((size_t)(w * 32 + bit) << 9) + n0);
                        rec[0] += wv.x; rec[1] += wv.y; rec[2] += wv.z; rec[3] += wv.w;
                    }
                }
            }

            const float Iin[4] = {It4.x, It4.y, It4.z, It4.w};
            float s[4];
            int spiked = 0;
#pragma unroll
            for (int k = 0; k < 4; ++k) {
                rr[k] = rr[k] * e_syn + rec[k];
                psc[k] = psc[k] * e_syn + KP * rr[k];
                v[k] = v[k] + a_mem * (VR - v[k]) + a_mem * (Iin[k] + psc[k] + asc[k]);
                bool inref = rcnt[k] > 0;
                if (inref) v[k] = VR;
                s[k] = (v[k] - VTH >= 0.0f) ? 1.0f : 0.0f;
                if (s[k] > 0.0f) { v[k] = VR; rcnt[k] = 5; spiked = 1; }
                else             { rcnt[k] = inref ? rcnt[k] - 1 : 0; }
                asc[k] = asc[k] * e_asc + AA * s[k];
                f[k] = (tt == 0) ? s[k] : (alpha * f[k] + oma * s[k]);
                if (tt >= startT) fsum[k] += f[k];
            }

            if (writeHist) {
                size_t idx = (size_t)tt * BN + (size_t)b * N_ + n0;
                *(float4*)(vlt + idx) = make_float4(v[0], v[1], v[2], v[3]);
#pragma unroll
                for (int k = 0; k < 4; ++k) {
                    if (s[k] != 0.0f)   spk[idx + k] = s[k];
                    if (psc[k] != 0.0f) pscO[idx + k] = psc[k];
                    if (f[k] != 0.0f)   filt[idx + k] = f[k];
                }
            }

            int any = __syncthreads_or(spiked);
            if (any | prev_any) {
                const int wb = rb ^ 1;
                if (prev_any && tid < 16) smask[rb][tid] = 0u;  // consumed -> re-zero
                if (spiked) {
                    unsigned bits = 0u;
#pragma unroll
                    for (int k = 0; k < 4; ++k)
                        if (s[k] != 0.0f) bits |= 1u << (mbit0 + k);
                    atomicOr(&smask[wb][mword], bits);
                }
                __syncthreads();
                if (any) rb = wb;
            }
            prev_any = any;
        }
    }
    // remainder (T not multiple of 8): latency-exposed, <=7 steps
    for (int tt = Tm; tt < T; ++tt) {
        const float4 It4 = __ldg((const float4*)(Ibase + (size_t)tt * BN));
        float rec[4] = {0.f, 0.f, 0.f, 0.f};
        if (prev_any) {
#pragma unroll 1
            for (int w = 0; w < 16; ++w) {
                unsigned m = smask[rb][w];
                while (m) {
                    int bit = __ffs((int)m) - 1;
                    m &= (m - 1);
                    float4 wv = *(const float4*)(g_WT + ((size_t)(w * 32 + bit) << 9) + n0);
                    rec[0] += wv.x; rec[1] += wv.y; rec[2] += wv.z; rec[3] += wv.w;
                }
            }
        }
        const float Iin[4] = {It4.x, It4.y, It4.z, It4.w};
        float s[4];
        int spiked = 0;
#pragma unroll
        for (int k = 0; k < 4; ++k) {
            rr[k] = rr[k] * e_syn + rec[k];
            psc[k] = psc[k] * e_syn + KP * rr[k];
            v[k] = v[k] + a_mem * (VR - v[k]) + a_mem * (Iin[k] + psc[k] + asc[k]);
            bool inref = rcnt[k] > 0;
            if (inref) v[k] = VR;
            s[k] = (v[k] - VTH >= 0.0f) ? 1.0f : 0.0f;
            if (s[k] > 0.0f) { v[k] = VR; rcnt[k] = 5; spiked = 1; }
            else             { rcnt[k] = inref ? rcnt[k] - 1 : 0; }
            asc[k] = asc[k] * e_asc + AA * s[k];
            f[k] = (tt == 0) ? s[k] : (alpha * f[k] + oma * s[k]);
            if (tt >= startT) fsum[k] += f[k];
        }
        if (writeHist) {
            size_t idx = (size_t)tt * BN + (size_t)b * N_ + n0;
            *(float4*)(vlt + idx) = make_float4(v[0], v[1], v[2], v[3]);
#pragma unroll
            for (int k = 0; k < 4; ++k) {
                if (s[k] != 0.0f)   spk[idx + k] = s[k];
                if (psc[k] != 0.0f) pscO[idx + k] = psc[k];
                if (f[k] != 0.0f)   filt[idx + k] = f[k];
            }
        }
        int any = __syncthreads_or(spiked);
        if (any | prev_any) {
            const int wb = rb ^ 1;
            if (prev_any && tid < 16) smask[rb][tid] = 0u;
            if (spiked) {
                unsigned bits = 0u;
#pragma unroll
                for (int k = 0; k < 4; ++k)
                    if (s[k] != 0.0f) bits |= 1u << (mbit0 + k);
                atomicOr(&smask[wb][mword], bits);
            }
            __syncthreads();
            if (any) rb = wb;
        }
        prev_any = any;
    }

    // readout
    const float cnt = (float)(T - startT);
    const float osc = __ldg(osc_p);
    float a[4];
#pragma unroll
    for (int k = 0; k < 4; ++k) a[k] = (fsum[k] / cnt) * osc;
#pragma unroll 1
    for (int o = 0; o < O_; ++o) {
        float4 w4 = *(const float4*)(Wout + (size_t)o * N_ + n0);
        float val = a[0] * w4.x + a[1] * w4.y + a[2] * w4.z + a[3] * w4.w;
#pragma unroll
        for (int off = 16; off > 0; off >>= 1)
            val += __shfl_down_sync(0xffffffffu, val, off);
        if (lane == 0) sred[wid] = val;
        __syncthreads();
        if (tid == 0)
            out[b * O_ + o] = sred[0] + sred[1] + sred[2] + sred[3] + __ldg(bout + o);
        __syncthreads();
    }
}

extern "C" void kernel_launch(void* const* d_in, const int* in_sizes, int n_in,
                              void* d_out, int out_size) {
    const float* x    = (const float*)d_in[0];
    const float* Win  = (const float*)d_in[1];
    const float* isc  = (const float*)d_in[2];
    const float* Wrec = (const float*)d_in[3];
    const float* Wout = (const float*)d_in[4];
    const float* bout = (const float*)d_in[5];
    const float* osc  = (const float*)d_in[6];

    const int T = in_sizes[0] / (B_ * D_);
    float* out = (float*)d_out;
    const size_t TBN = (size_t)T * B_ * N_;
    const long long fullsz = (long long)B_ * O_ + 4LL * (long long)TBN;
    const int writeHist = ((long long)out_size >= fullsz) ? 1 : 0;
    float* spk = out + B_ * O_;
    float* vlt = spk + TBN;
    float* psc = vlt + TBN;
    float* flt = psc + TBN;

    const float e_syn = (float)exp((double)(-1.0f / 5.0f));
    const float e_asc = (float)exp((double)(-1.0f / 700.0f));
    const float alpha = (float)exp((double)(-1.0f / 20.0f));
    // int(T * (1.0 - 0.8)) truncates (float artifact): 199 for T=1000
    const int startT = (int)((double)T * (1.0 - 0.8));

    cudaFuncSetAttribute(iext_gemm, cudaFuncAttributeMaxDynamicSharedMemorySize, GEMM_SMEM);
    iext_gemm<<<dim3((T * B_) / GBM, N_ / GBN), 256, GEMM_SMEM>>>(x, Win, isc);

    // zero-fill spk (TBN) and psc+filt (2*TBN contiguous) — sim writes them sparsely
    if (writeHist)
        zfill<<<2048, 256>>>((float4*)spk, TBN / 4, (float4*)psc, (2 * TBN) / 4);

    wt_transpose<<<dim3(16, 16), dim3(32, 8)>>>(Wrec);

    sim_kernel<<<B_, 128>>>(Wout, bout, osc, out, spk, vlt, psc, flt,
                            T, startT, writeHist, e_syn, e_asc, alpha);
}

// round 6
// speedup vs baseline: 1.4524x; 1.4432x over previous
#include <cuda_runtime.h>
#include <math.h>

#define T_MAX 1000
#define B_ 64
#define D_ 128
#define N_ 512
#define O_ 10

#define SIM_BLKS 64
#define TP_BLKS 256
#define ZF_BLKS 384

__device__ float g_Iext[(size_t)T_MAX * B_ * N_];  // 131 MB scratch
__device__ float g_WT[N_ * N_];                    // W_rec transposed
__device__ unsigned g_cnt[512];                    // per-time-tile gemm completion (4 each)
__device__ unsigned g_tp;                          // transpose done counter
__device__ unsigned g_zf;                          // zfill done counter

__global__ void reset_kernel() {
    int i = threadIdx.x;
    if (i < 512) g_cnt[i] = 0u;
    if (i == 0) { g_tp = 0u; g_zf = 0u; }
}

__device__ __forceinline__ unsigned ldacq(const unsigned* p) {
    unsigned v;
    asm volatile("ld.acquire.gpu.u32 %0, [%1];" : "=r"(v) : "l"(p));
    return v;
}

// warp0: spin until g_cnt[xbase .. xbase+nx-1] all >= 4 (x > xmax exempt)
__device__ __forceinline__ void verify_x(int tid, int xbase, int nx, int xmax) {
    if (tid < 32) {
        int x = xbase + tid;
        bool need = (tid < nx) && (x <= xmax);
        for (;;) {
            bool ok = !need || (ldacq(&g_cnt[x]) >= 4u);
            if (__ballot_sync(0xffffffffu, ok) == 0xffffffffu) break;
            __nanosleep(64);
        }
    }
}

// ---------------- GEMM tile geometry ----------------
#define GBM 128
#define GBN 128
#define GKH 64
#define A_LD 68
#define B_LD 130
#define GEMM_SMEM ((GBM * A_LD + GKH * B_LD) * 4)

__global__ __launch_bounds__(256, 2) void mega(
    const float* __restrict__ X, const float* __restrict__ Win,
    const float* __restrict__ sc_p, const float* __restrict__ Wrec,
    const float* __restrict__ Wout, const float* __restrict__ bout,
    const float* __restrict__ osc_p,
    float* __restrict__ out, float* __restrict__ spk, float* __restrict__ vlt,
    float* __restrict__ pscO, float* __restrict__ filt,
    int T, int startT, int writeHist,
    float e_syn, float e_asc, float alpha)
{
    const int bid = blockIdx.x;
    const int tid = threadIdx.x;
    const size_t TBN = (size_t)T * B_ * N_;
    const int BN = B_ * N_;

    // ================= GEMM role =================
    if (bid >= SIM_BLKS + TP_BLKS + ZF_BLKS) {
        extern __shared__ float sm[];
        float* As = sm;
        float* Bs = sm + GBM * A_LD;
        const int idg = bid - (SIM_BLKS + TP_BLKS + ZF_BLKS);
        const int x = idg >> 2;
        const int y = idg & 3;
        const int m0 = x * GBM;
        const int n0 = y * GBN;
        const float sc = __ldg(sc_p);

        const int tm  = (tid >> 4) * 8;
        const int tn2 = (tid & 15) * 2;
        unsigned long long acc[8][4];
#pragma unroll
        for (int i = 0; i < 8; ++i)
#pragma unroll
            for (int j = 0; j < 4; ++j) acc[i][j] = 0ull;

        const int c4 = (tid & 15) * 4;
        const int rbase = tid >> 4;

#pragma unroll 1
        for (int kb = 0; kb < 2; ++kb) {
            if (kb) __syncthreads();
#pragma unroll
            for (int p = 0; p < 8; ++p) {
                int m = rbase + p * 16;
                float4 xv = *(const float4*)(X + (size_t)(m0 + m) * D_ + kb * GKH + c4);
                xv.x *= sc; xv.y *= sc; xv.z *= sc; xv.w *= sc;
                *(float4*)(As + m * A_LD + c4) = xv;
            }
#pragma unroll
            for (int p = 0; p < 8; ++p) {
                int id = tid + p * 256;
                int nn = id >> 4;
                int cc = (id & 15) * 4;
                float4 wv = *(const float4*)(Win + (size_t)(n0 + nn) * D_ + kb * GKH + cc);
                Bs[(cc + 0) * B_LD + nn] = wv.x;
                Bs[(cc + 1) * B_LD + nn] = wv.y;
                Bs[(cc + 2) * B_LD + nn] = wv.z;
                Bs[(cc + 3) * B_LD + nn] = wv.w;
            }
            __syncthreads();

#pragma unroll 2
            for (int k = 0; k < GKH; ++k) {
                unsigned long long b2[4];
#pragma unroll
                for (int j = 0; j < 4; ++j) {
                    float2 bb = *(const float2*)(Bs + k * B_LD + tn2 + 32 * j);
                    asm("mov.b64 %0, {%1,%2};" : "=l"(b2[j]) : "f"(bb.x), "f"(bb.y));
                }
#pragma unroll
                for (int i = 0; i < 8; ++i) {
                    float a = As[(tm + i) * A_LD + k];
                    unsigned long long a2;
                    asm("mov.b64 %0, {%1,%1};" : "=l"(a2) : "f"(a));
#pragma unroll
                    for (int j = 0; j < 4; ++j)
                        asm("fma.rn.f32x2 %0, %1, %2, %0;" : "+l"(acc[i][j]) : "l"(a2), "l"(b2[j]));
                }
            }
        }
#pragma unroll
        for (int i = 0; i < 8; ++i) {
            float* orow = g_Iext + (size_t)(m0 + tm + i) * N_ + n0 + tn2;
#pragma unroll
            for (int j = 0; j < 4; ++j) {
                float2 o;
                asm("mov.b64 {%0,%1}, %2;" : "=f"(o.x), "=f"(o.y) : "l"(acc[i][j]));
                *(float2*)(orow + 32 * j) = o;
            }
        }
        __threadfence();
        __syncthreads();
        if (tid == 0) atomicAdd(&g_cnt[x], 1u);
        return;
    }

    // ================= zfill role =================
    if (bid >= SIM_BLKS + TP_BLKS) {
        if (writeHist) {
            const size_t na = TBN / 4, nb = (2 * TBN) / 4;
            float4* a4 = (float4*)spk;
            float4* b4 = (float4*)pscO;   // psc+filt contiguous
            float4 z = make_float4(0.f, 0.f, 0.f, 0.f);
            size_t i = (size_t)(bid - SIM_BLKS - TP_BLKS) * 256 + tid;
            size_t stride = (size_t)ZF_BLKS * 256;
            for (; i < na + nb; i += stride) {
                if (i < na) a4[i] = z;
                else        b4[i - na] = z;
            }
        }
        __threadfence();
        __syncthreads();
        if (tid == 0) atomicAdd(&g_zf, 1u);
        return;
    }

    // ================= transpose role =================
    if (bid >= SIM_BLKS) {
        __shared__ float tile[32][33];
        const int id2 = bid - SIM_BLKS;
        const int bx = (id2 & 15) * 32, by = (id2 >> 4) * 32;
        const int tx = tid & 31, ty = tid >> 5;  // 32 x 8
#pragma unroll
        for (int i = 0; i < 32; i += 8)
            tile[ty + i][tx] = Wrec[(size_t)(by + ty + i) * N_ + (bx + tx)];
        __syncthreads();
#pragma unroll
        for (int i = 0; i < 32; i += 8)
            g_WT[(size_t)(bx + ty + i) * N_ + (by + tx)] = tile[tx][ty + i];
        __threadfence();
        __syncthreads();
        if (tid == 0) atomicAdd(&g_tp, 1u);
        return;
    }

    // ================= sim role: 1 CTA/batch, 256 thr, 2 neurons/thread =================
    {
        const int b = blockIdx.x;
        const int lane = tid & 31, wid = tid >> 5;
        const int n0 = tid * 2;
        const int mword = tid >> 4;
        const int mbit0 = (tid & 15) * 2;
        const int xmax = ((T - 1) >> 1);

        __shared__ unsigned smask[2][16];
        __shared__ float sred[8];
        __shared__ int s_ever;
        if (tid < 16) { smask[0][tid] = 0u; smask[1][tid] = 0u; }
        if (tid == 0) s_ever = 0;

        verify_x(tid, 0, 8, xmax);    // times 0..15 safe
        __syncthreads();

        const float a_mem = 0.05f, VR = -60.0f, VTH = -45.0f, KP = 0.2f, AA = -0.2f;
        const float oma = 1.0f - alpha;
        float v[2], asc[2], rr[2], psc[2], f[2], fsum[2];
        int rcnt[2];
#pragma unroll
        for (int k = 0; k < 2; ++k) {
            v[k] = VR; asc[k] = 0.f; rr[k] = 0.f; psc[k] = 0.f;
            f[k] = 0.f; fsum[k] = 0.f; rcnt[k] = 0;
        }
        const float* Ibase = g_Iext + (size_t)b * N_ + n0;

        float2 pre[8];
#pragma unroll
        for (int j = 0; j < 8; ++j) {
            if (j < T) pre[j] = *(const float2*)(Ibase + (size_t)j * BN);
            else       pre[j] = make_float2(0.f, 0.f);
        }

        int rb = 0, prev_any = 0;
        const int Tm = T & ~7;
        for (int t0 = 0; t0 < Tm; t0 += 8) {
            verify_x(tid, (t0 >> 1) + 8, 4, xmax);   // safety for next block's prefetches
#pragma unroll
            for (int j = 0; j < 8; ++j) {
                const int tt = t0 + j;
                const float2 It2 = pre[j];
                if (tt + 8 < T) pre[j] = *(const float2*)(Ibase + (size_t)(tt + 8) * BN);

                float rec[2] = {0.f, 0.f};
                if (prev_any) {
#pragma unroll 1
                    for (int w = 0; w < 16; ++w) {
                        unsigned m = smask[rb][w];
                        while (m) {
                            int bit = __ffs((int)m) - 1;
                            m &= (m - 1);
                            float2 wv = *(const float2*)(g_WT + ((size_t)(w * 32 + bit) << 9) + n0);
                            rec[0] += wv.x; rec[1] += wv.y;
                        }
                    }
                }

                const float Iin[2] = {It2.x, It2.y};
                float s[2];
                int spiked = 0;
#pragma unroll
                for (int k = 0; k < 2; ++k) {
                    rr[k] = rr[k] * e_syn + rec[k];
                    psc[k] = psc[k] * e_syn + KP * rr[k];
                    v[k] = v[k] + a_mem * (VR - v[k]) + a_mem * (Iin[k] + psc[k] + asc[k]);
                    bool inref = rcnt[k] > 0;
                    if (inref) v[k] = VR;
                    s[k] = (v[k] - VTH >= 0.0f) ? 1.0f : 0.0f;
                    if (s[k] > 0.0f) { v[k] = VR; rcnt[k] = 5; spiked = 1; }
                    else             { rcnt[k] = inref ? rcnt[k] - 1 : 0; }
                    asc[k] = asc[k] * e_asc + AA * s[k];
                    f[k] = (tt == 0) ? s[k] : (alpha * f[k] + oma * s[k]);
                    if (tt >= startT) fsum[k] += f[k];
                }

                int any = __syncthreads_or(spiked);
                int ever = s_ever;
                if (any && !ever) {
                    // first spike in this batch: wait for transpose + zfill (once)
                    if (tid == 0) {
                        while (ldacq(&g_tp) < (unsigned)TP_BLKS) __nanosleep(64);
                        if (writeHist)
                            while (ldacq(&g_zf) < (unsigned)ZF_BLKS) __nanosleep(64);
                        s_ever = 1;
                    }
                    __syncthreads();
                    ever = 1;
                }

                if (writeHist) {
                    size_t idx = (size_t)tt * BN + (size_t)b * N_ + n0;
                    *(float2*)(vlt + idx) = make_float2(v[0], v[1]);
                    if (ever) {
#pragma unroll
                        for (int k = 0; k < 2; ++k) {
                            if (s[k] != 0.0f)   spk[idx + k] = s[k];
                            if (psc[k] != 0.0f) pscO[idx + k] = psc[k];
                            if (f[k] != 0.0f)   filt[idx + k] = f[k];
                        }
                    }
                }

                if (any | prev_any) {
                    const int wb = rb ^ 1;
                    if (prev_any && tid < 16) smask[rb][tid] = 0u;
                    if (spiked) {
                        unsigned bits = 0u;
#pragma unroll
                        for (int k = 0; k < 2; ++k)
                            if (s[k] != 0.0f) bits |= 1u << (mbit0 + k);
                        atomicOr(&smask[wb][mword], bits);
                    }
                    __syncthreads();
                    if (any) rb = wb;
                }
                prev_any = any;
            }
        }

        // remainder steps (T % 8)
        if (Tm < T) {
            if (tid == 0)
                for (int x = (Tm >> 1); x <= xmax; ++x)
                    while (ldacq(&g_cnt[x]) < 4u) __nanosleep(64);
            __syncthreads();
            for (int tt = Tm; tt < T; ++tt) {
                const float2 It2 = *(const float2*)(Ibase + (size_t)tt * BN);
                float rec[2] = {0.f, 0.f};
                if (prev_any) {
#pragma unroll 1
                    for (int w = 0; w < 16; ++w) {
                        unsigned m = smask[rb][w];
                        while (m) {
                            int bit = __ffs((int)m) - 1;
                            m &= (m - 1);
                            float2 wv = *(const float2*)(g_WT + ((size_t)(w * 32 + bit) << 9) + n0);
                            rec[0] += wv.x; rec[1] += wv.y;
                        }
                    }
                }
                const float Iin[2] = {It2.x, It2.y};
                float s[2];
                int spiked = 0;
#pragma unroll
                for (int k = 0; k < 2; ++k) {
                    rr[k] = rr[k] * e_syn + rec[k];
                    psc[k] = psc[k] * e_syn + KP * rr[k];
                    v[k] = v[k] + a_mem * (VR - v[k]) + a_mem * (Iin[k] + psc[k] + asc[k]);
                    bool inref = rcnt[k] > 0;
                    if (inref) v[k] = VR;
                    s[k] = (v[k] - VTH >= 0.0f) ? 1.0f : 0.0f;
                    if (s[k] > 0.0f) { v[k] = VR; rcnt[k] = 5; spiked = 1; }
                    else             { rcnt[k] = inref ? rcnt[k] - 1 : 0; }
                    asc[k] = asc[k] * e_asc + AA * s[k];
                    f[k] = (tt == 0) ? s[k] : (alpha * f[k] + oma * s[k]);
                    if (tt >= startT) fsum[k] += f[k];
                }
                int any = __syncthreads_or(spiked);
                int ever = s_ever;
                if (any && !ever) {
                    if (tid == 0) {
                        while (ldacq(&g_tp) < (unsigned)TP_BLKS) __nanosleep(64);
                        if (writeHist)
                            while (ldacq(&g_zf) < (unsigned)ZF_BLKS) __nanosleep(64);
                        s_ever = 1;
                    }
                    __syncthreads();
                    ever = 1;
                }
                if (writeHist) {
                    size_t idx = (size_t)tt * BN + (size_t)b * N_ + n0;
                    *(float2*)(vlt + idx) = make_float2(v[0], v[1]);
                    if (ever) {
#pragma unroll
                        for (int k = 0; k < 2; ++k) {
                            if (s[k] != 0.0f)   spk[idx + k] = s[k];
                            if (psc[k] != 0.0f) pscO[idx + k] = psc[k];
                            if (f[k] != 0.0f)   filt[idx + k] = f[k];
                        }
                    }
                }
                if (any | prev_any) {
                    const int wb = rb ^ 1;
                    if (prev_any && tid < 16) smask[rb][tid] = 0u;
                    if (spiked) {
                        unsigned bits = 0u;
#pragma unroll
                        for (int k = 0; k < 2; ++k)
                            if (s[k] != 0.0f) bits |= 1u << (mbit0 + k);
                        atomicOr(&smask[wb][mword], bits);
                    }
                    __syncthreads();
                    if (any) rb = wb;
                }
                prev_any = any;
            }
        }

        // readout
        const float cnt = (float)(T - startT);
        const float osc = __ldg(osc_p);
        float a0 = (fsum[0] / cnt) * osc;
        float a1 = (fsum[1] / cnt) * osc;
#pragma unroll 1
        for (int o = 0; o < O_; ++o) {
            float2 w2 = *(const float2*)(Wout + (size_t)o * N_ + n0);
            float val = a0 * w2.x + a1 * w2.y;
#pragma unroll
            for (int off = 16; off > 0; off >>= 1)
                val += __shfl_down_sync(0xffffffffu, val, off);
            if (lane == 0) sred[wid] = val;
            __syncthreads();
            if (tid == 0) {
                float acc = __ldg(bout + o);
#pragma unroll
                for (int q = 0; q < 8; ++q) acc += sred[q];
                out[b * O_ + o] = acc;
            }
            __syncthreads();
        }
    }
}

extern "C" void kernel_launch(void* const* d_in, const int* in_sizes, int n_in,
                              void* d_out, int out_size) {
    const float* x    = (const float*)d_in[0];
    const float* Win  = (const float*)d_in[1];
    const float* isc  = (const float*)d_in[2];
    const float* Wrec = (const float*)d_in[3];
    const float* Wout = (const float*)d_in[4];
    const float* bout = (const float*)d_in[5];
    const float* osc  = (const float*)d_in[6];

    const int T = in_sizes[0] / (B_ * D_);
    float* out = (float*)d_out;
    const size_t TBN = (size_t)T * B_ * N_;
    const long long fullsz = (long long)B_ * O_ + 4LL * (long long)TBN;
    const int writeHist = ((long long)out_size >= fullsz) ? 1 : 0;
    float* spk = out + B_ * O_;
    float* vlt = spk + TBN;
    float* psc = vlt + TBN;
    float* flt = psc + TBN;

    const float e_syn = (float)exp((double)(-1.0f / 5.0f));
    const float e_asc = (float)exp((double)(-1.0f / 700.0f));
    const float alpha = (float)exp((double)(-1.0f / 20.0f));
    // int(T * (1.0 - 0.8)) truncates (float artifact): 199 for T=1000
    const int startT = (int)((double)T * (1.0 - 0.8));

    const int NX = (T * B_) / GBM;   // time-tiles (2 steps each), T*B divisible by 128
    const int grid = SIM_BLKS + TP_BLKS + ZF_BLKS + NX * 4;

    reset_kernel<<<1, 512>>>();

    cudaFuncSetAttribute(mega, cudaFuncAttributeMaxDynamicSharedMemorySize, GEMM_SMEM);
    mega<<<grid, 256, GEMM_SMEM>>>(x, Win, isc, Wrec, Wout, bout, osc,
                                   out, spk, vlt, psc, flt,
                                   T, startT, writeHist, e_syn, e_asc, alpha);
}